// round 7
// baseline (speedup 1.0000x reference)
#include <cuda_runtime.h>
#include <cstdint>

// ---------------- problem constants ----------------
#define NB    32
#define CIN   256
#define COUTC 256
#define TT    128
#define VV    25
#define KK    3
#define QQ    (TT*VV)       // 3200 pixels per n
#define QTOT  (NB*QQ)       // 102400
#define MTOT  768           // reduction dim m = (k,ci)
#define BN_EPS 1e-5f
#define CNT   (NB*TT*VV)    // 102400 per-channel count

// ---------------- GEMM tiling ----------------
#define BM    128           // c tile
#define BNQ   128           // q tile
#define BK    32
#define NKC   24            // 768/32
#define NQT2  800           // 102400/128
#define NPART 3200          // partials per channel

// padded smem rows: 32 floats + 4 pad
#define ROWF    36
#define TILE_F  (BM*ROWF)           // 4608 floats per tile
#define SMEM_GEMM (4*TILE_F*4)      // 73728 bytes (A0,A1,X0,X1)

typedef unsigned long long ull;

// physical permutation of the K index within each aligned 8-block:
// logical i (0..7) -> (i&3)*2 + (i>>2). Makes {k, k+4} adjacent for LDS.64 frags.
__host__ __device__ __forceinline__ int perm8(int m) {
    return (m & ~7) | ((m & 3) << 1) | ((m >> 2) & 1);
}

// ---------------- device scratch ----------------
__device__ __align__(16) float g_W2[COUTC * MTOT];             // tf32 W [c][m_phys]
__device__ __align__(16) float g_XA[(size_t)QTOT * MTOT];      // tf32 folded input [q][m_phys]
__device__ __align__(16) float g_z [(size_t)NB * COUTC * QQ];  // pre-BN activations
__device__ float g_zb  [COUTC * VV];
__device__ float g_psum[COUTC * NPART];
__device__ float g_psq [COUTC * NPART];
__device__ float g_ss  [2 * COUTC];

// ---------------- helpers ----------------
__device__ __forceinline__ uint32_t smem_u32(const void* p) {
    uint32_t a;
    asm("{ .reg .u64 t; cvta.to.shared.u64 t, %1; cvt.u32.u64 %0, t; }" : "=r"(a) : "l"(p));
    return a;
}
__device__ __forceinline__ ull pack2(float lo, float hi) {
    ull r; asm("mov.b64 %0, {%1,%2};" : "=l"(r) : "f"(lo), "f"(hi)); return r;
}
__device__ __forceinline__ void unpack2(ull a, float &lo, float &hi) {
    asm("mov.b64 {%0,%1}, %2;" : "=f"(lo), "=f"(hi) : "l"(a));
}
__device__ __forceinline__ ull fma2(ull a, ull b, ull c) {
    ull d; asm("fma.rn.f32x2 %0, %1, %2, %3;" : "=l"(d) : "l"(a), "l"(b), "l"(c)); return d;
}
__device__ __forceinline__ float totf32(float f) {
    uint32_t u; asm("cvt.rna.tf32.f32 %0, %1;" : "=r"(u) : "f"(f));
    return __uint_as_float(u);
}

#define CP_ASYNC16(dst, src) \
    asm volatile("cp.async.cg.shared.global [%0], [%1], 16;" :: "r"(dst), "l"(src))
#define CP_COMMIT() asm volatile("cp.async.commit_group;" ::: "memory")
#define CP_WAIT1()  asm volatile("cp.async.wait_group 1;"  ::: "memory")

__device__ __forceinline__ void mma_tf32(float* c, const uint32_t* a, const uint32_t* b) {
    asm volatile(
        "mma.sync.aligned.m16n8k8.row.col.f32.tf32.tf32.f32 "
        "{%0,%1,%2,%3}, {%4,%5,%6,%7}, {%8,%9}, {%0,%1,%2,%3};"
        : "+f"(c[0]), "+f"(c[1]), "+f"(c[2]), "+f"(c[3])
        : "r"(a[0]), "r"(a[1]), "r"(a[2]), "r"(a[3]), "r"(b[0]), "r"(b[1]));
}

// ---------------- kernel: W re-layout (tf32 + k-perm) ----------------
// W[o=k*256+c][ci] -> W2[c][perm(k*256+ci)]
__global__ void k_w2(const float* __restrict__ W) {
    const int o = blockIdx.x;
    const int ci = threadIdx.x;
    const int c = o & 255, k = o >> 8;
    g_W2[c * MTOT + k * 256 + perm8(ci)] = totf32(W[o * 256 + ci]);
}

// ---------------- kernel: bias fold term ----------------
__global__ void k_zb(const float* __restrict__ A, const float* __restrict__ b) {
    const int w = blockIdx.x;
    const int c = threadIdx.x;
    float s = 0.f;
    for (int k = 0; k < KK; k++) {
        float sa = 0.f;
        for (int v = 0; v < VV; v++) sa += A[(k * VV + v) * VV + w];
        s += b[k * 256 + c] * sa;
    }
    g_zb[c * VV + w] = s;
}

// ---------------- kernel: fold adjacency into input (tf32 + k-perm) ----------------
__global__ __launch_bounds__(128) void k_prep(const float* __restrict__ x,
                                              const float* __restrict__ A) {
    __shared__ ull As2[KK][VV][13];
    const int bx = blockIdx.x;
    const int n = bx >> 7;
    const int t = bx & (TT - 1);
    const int tid = threadIdx.x;
    const int pt = perm8(tid);           // permuted ci position (tid < 128)

    for (int i = tid; i < KK * VV * 13; i += 128) {
        int k = i / (VV * 13);
        int r = i - k * (VV * 13);
        int v = r / 13, j = r - v * 13;
        float lo = A[(k * VV + v) * VV + 2 * j];
        float hi = (2 * j + 1 < VV) ? A[(k * VV + v) * VV + 2 * j + 1] : 0.f;
        As2[k][v][j] = pack2(lo, hi);
    }

    float xa[VV], xb[VV];
    {
        const float* pa = x + ((size_t)(n * CIN + tid) * TT + t) * VV;
        const float* pb = x + ((size_t)(n * CIN + tid + 128) * TT + t) * VV;
        #pragma unroll
        for (int v = 0; v < VV; v++) { xa[v] = pa[v]; xb[v] = pb[v]; }
    }
    __syncthreads();

    for (int k = 0; k < KK; k++) {
        ull za[13], zq[13];
        #pragma unroll
        for (int j = 0; j < 13; j++) { za[j] = 0ull; zq[j] = 0ull; }
        for (int v = 0; v < VV; v++) {
            const ull a2 = pack2(xa[v], xa[v]);
            const ull b2 = pack2(xb[v], xb[v]);
            #pragma unroll
            for (int j = 0; j < 13; j++) {
                const ull m = As2[k][v][j];
                za[j] = fma2(a2, m, za[j]);
                zq[j] = fma2(b2, m, zq[j]);
            }
        }
        const size_t rowbase = ((size_t)n * QQ + t * VV) * MTOT + k * 256;
        #pragma unroll
        for (int j = 0; j < 13; j++) {
            float lo, hi;
            unpack2(za[j], lo, hi);
            g_XA[rowbase + (size_t)(2 * j) * MTOT + pt] = totf32(lo);
            if (2 * j + 1 < VV) g_XA[rowbase + (size_t)(2 * j + 1) * MTOT + pt] = totf32(hi);
            unpack2(zq[j], lo, hi);
            g_XA[rowbase + (size_t)(2 * j) * MTOT + 128 + pt] = totf32(lo);
            if (2 * j + 1 < VV) g_XA[rowbase + (size_t)(2 * j + 1) * MTOT + 128 + pt] = totf32(hi);
        }
    }
}

// ---------------- kernel: warp-MMA tf32 GEMM + fused epilogue ----------------
__global__ __launch_bounds__(256, 3) void k_gemm() {
    extern __shared__ float sm[];
    float* Asm = sm;
    float* Xsm = sm + 2 * TILE_F;

    const int tid  = threadIdx.x;
    const int wid  = tid >> 5;
    const int lane = tid & 31;
    const int gid  = lane >> 2;
    const int tg   = lane & 3;
    const int wm   = wid >> 2;       // 0..1 -> 64 c-rows
    const int wn   = wid & 3;        // 0..3 -> 32 q-cols

    const int c0 = blockIdx.x * BM;
    const int q0 = blockIdx.y * BNQ;
    const int n    = q0 / QQ;
    const int qloc = q0 - n * QQ;

    const int lrow = tid >> 3;
    const int lc4  = tid & 7;
    const uint32_t sbase = smem_u32(sm);

    auto load_tiles = [&](int kc, int s) {
        const float* ga = g_W2 + (size_t)(c0 + lrow) * MTOT + kc * BK + lc4 * 4;
        const float* gx = g_XA + (size_t)(q0 + lrow) * MTOT + kc * BK + lc4 * 4;
        uint32_t da = sbase + (uint32_t)(s * TILE_F + lrow * ROWF + lc4 * 4) * 4;
        uint32_t dx = sbase + (uint32_t)((2 + s) * TILE_F + lrow * ROWF + lc4 * 4) * 4;
        #pragma unroll
        for (int u = 0; u < 4; u++) {
            CP_ASYNC16(da + u * 32 * ROWF * 4, ga + (size_t)u * 32 * MTOT);
            CP_ASYNC16(dx + u * 32 * ROWF * 4, gx + (size_t)u * 32 * MTOT);
        }
    };

    float acc[4][4][4];
    #pragma unroll
    for (int mf = 0; mf < 4; mf++)
        #pragma unroll
        for (int nf = 0; nf < 4; nf++)
            #pragma unroll
            for (int j = 0; j < 4; j++) acc[mf][nf][j] = 0.f;

    load_tiles(0, 0);
    CP_COMMIT();

    for (int kc = 0; kc < NKC; kc++) {
        const int s = kc & 1;
        if (kc + 1 < NKC) load_tiles(kc + 1, s ^ 1);
        CP_COMMIT();
        CP_WAIT1();
        __syncthreads();

        // k-perm layout: logical {kk, kk+4} sit at physical {k8*8+tg*2, +1}
        const float* AbRow = Asm + s * TILE_F + (wm * 64 + gid) * ROWF;
        const float* XbRow = Xsm + s * TILE_F + (wn * 32 + gid) * ROWF;
        #pragma unroll
        for (int k8 = 0; k8 < 4; k8++) {
            const int bo = k8 * 8 + tg * 2;
            uint32_t afr[4][4];
            #pragma unroll
            for (int mf = 0; mf < 4; mf++) {
                const float2 lo = *(const float2*)(AbRow + mf * 16 * ROWF + bo);
                const float2 hi = *(const float2*)(AbRow + mf * 16 * ROWF + 8 * ROWF + bo);
                afr[mf][0] = __float_as_uint(lo.x);
                afr[mf][1] = __float_as_uint(hi.x);
                afr[mf][2] = __float_as_uint(lo.y);
                afr[mf][3] = __float_as_uint(hi.y);
            }
            uint32_t bfr[4][2];
            #pragma unroll
            for (int nf = 0; nf < 4; nf++) {
                const float2 bb = *(const float2*)(XbRow + nf * 8 * ROWF + bo);
                bfr[nf][0] = __float_as_uint(bb.x);
                bfr[nf][1] = __float_as_uint(bb.y);
            }
            #pragma unroll
            for (int mf = 0; mf < 4; mf++)
                #pragma unroll
                for (int nf = 0; nf < 4; nf++)
                    mma_tf32(acc[mf][nf], afr[mf], bfr[nf]);
        }
        __syncthreads();
    }

    // ---- epilogue: +zb, z write, BN partials ----
    float s1[4][2], s2[4][2];
    #pragma unroll
    for (int mf = 0; mf < 4; mf++) { s1[mf][0] = s1[mf][1] = 0.f; s2[mf][0] = s2[mf][1] = 0.f; }

    #pragma unroll
    for (int mf = 0; mf < 4; mf++) {
        const int r0 = c0 + wm * 64 + mf * 16 + gid;
        #pragma unroll
        for (int nf = 0; nf < 4; nf++) {
            const int col = qloc + wn * 32 + nf * 8 + tg * 2;
            const int w0 = col % VV;
            const int w1 = (w0 + 1 == VV) ? 0 : w0 + 1;
            const float zb00 = g_zb[r0 * VV + w0],       zb01 = g_zb[r0 * VV + w1];
            const float zb10 = g_zb[(r0 + 8) * VV + w0], zb11 = g_zb[(r0 + 8) * VV + w1];
            float v00 = acc[mf][nf][0] + zb00;
            float v01 = acc[mf][nf][1] + zb01;
            float v10 = acc[mf][nf][2] + zb10;
            float v11 = acc[mf][nf][3] + zb11;
            s1[mf][0] += v00 + v01;  s2[mf][0] += v00 * v00 + v01 * v01;
            s1[mf][1] += v10 + v11;  s2[mf][1] += v10 * v10 + v11 * v11;
            float* zp0 = g_z + (size_t)(n * COUTC + r0) * QQ + col;
            float* zp1 = g_z + (size_t)(n * COUTC + r0 + 8) * QQ + col;
            *(float2*)zp0 = make_float2(v00, v01);
            *(float2*)zp1 = make_float2(v10, v11);
        }
    }
    #pragma unroll
    for (int mf = 0; mf < 4; mf++)
        #pragma unroll
        for (int h = 0; h < 2; h++) {
            s1[mf][h] += __shfl_xor_sync(0xffffffffu, s1[mf][h], 1);
            s1[mf][h] += __shfl_xor_sync(0xffffffffu, s1[mf][h], 2);
            s2[mf][h] += __shfl_xor_sync(0xffffffffu, s2[mf][h], 1);
            s2[mf][h] += __shfl_xor_sync(0xffffffffu, s2[mf][h], 2);
        }
    if (tg == 0) {
        const int slot = blockIdx.y * 4 + wn;
        #pragma unroll
        for (int mf = 0; mf < 4; mf++)
            #pragma unroll
            for (int h = 0; h < 2; h++) {
                const int r = c0 + wm * 64 + mf * 16 + gid + h * 8;
                g_psum[r * NPART + slot] = s1[mf][h];
                g_psq [r * NPART + slot] = s2[mf][h];
            }
    }
}

// ---------------- kernel: finalize BN stats ----------------
__global__ void k_stats(const float* __restrict__ gamma, const float* __restrict__ beta) {
    const int c = blockIdx.x;
    const int tid = threadIdx.x;
    float s1 = 0.f, s2 = 0.f;
    const float* ps = g_psum + c * NPART;
    const float* pq = g_psq  + c * NPART;
    for (int i = tid; i < NPART; i += 256) { s1 += ps[i]; s2 += pq[i]; }
    __shared__ float r1[256], r2[256];
    r1[tid] = s1; r2[tid] = s2;
    __syncthreads();
    for (int s = 128; s > 0; s >>= 1) {
        if (tid < s) { r1[tid] += r1[tid + s]; r2[tid] += r2[tid + s]; }
        __syncthreads();
    }
    if (tid == 0) {
        const float inv  = 1.0f / (float)CNT;
        const float mean = r1[0] * inv;
        const float var  = r2[0] * inv - mean * mean;
        const float sc   = gamma[c] * rsqrtf(var + BN_EPS);
        g_ss[c]         = sc;
        g_ss[COUTC + c] = beta[c] - mean * sc;
    }
}

// ---------------- kernel: normalize + ReLU ----------------
__global__ void k_norm(float* __restrict__ out) {
    const int i4 = blockIdx.x * blockDim.x + threadIdx.x;
    const int c = (i4 / 800) & (COUTC - 1);
    const float sc = g_ss[c];
    const float sh = g_ss[COUTC + c];
    const float4 z = ((const float4*)g_z)[i4];
    float4 o;
    o.x = fmaxf(0.f, fmaf(z.x, sc, sh));
    o.y = fmaxf(0.f, fmaf(z.y, sc, sh));
    o.z = fmaxf(0.f, fmaf(z.z, sc, sh));
    o.w = fmaxf(0.f, fmaf(z.w, sc, sh));
    ((float4*)out)[i4] = o;
}

// ---------------- launch ----------------
extern "C" void kernel_launch(void* const* d_in, const int* in_sizes, int n_in,
                              void* d_out, int out_size) {
    const float* x     = (const float*)d_in[0];
    const float* A     = (const float*)d_in[1];
    const float* W     = (const float*)d_in[2];
    const float* b     = (const float*)d_in[3];
    const float* gamma = (const float*)d_in[4];
    const float* beta  = (const float*)d_in[5];
    float* out = (float*)d_out;

    cudaFuncSetAttribute(k_gemm, cudaFuncAttributeMaxDynamicSharedMemorySize, SMEM_GEMM);

    k_w2  <<<MTOT, 256>>>(W);
    k_zb  <<<VV, 256>>>(A, b);
    k_prep<<<NB * TT, 128>>>(x, A);
    k_gemm<<<dim3(2, NQT2), 256, SMEM_GEMM>>>();
    k_stats<<<COUTC, 256>>>(gamma, beta);
    k_norm<<<(NB * COUTC * TT * VV / 4) / 256, 256>>>(out);
}

// round 8
// speedup vs baseline: 1.7380x; 1.7380x over previous
#include <cuda_runtime.h>
#include <cstdint>

// ---------------- problem constants ----------------
#define NB    32
#define CIN   256
#define COUTC 256
#define TT    128
#define VV    25
#define KK    3
#define QQ    (TT*VV)       // 3200 pixels per n
#define QTOT  (NB*QQ)       // 102400
#define MTOT  768           // reduction dim m = (k,ci)
#define BN_EPS 1e-5f
#define CNT   (NB*TT*VV)    // 102400 per-channel count

// ---------------- GEMM tiling ----------------
#define BM    128           // c tile
#define BNQ   128           // q tile
#define BK    32
#define NKC   24            // 768/32
#define NQT2  800           // 102400/128
#define NPART 3200          // partials per channel

// padded smem rows: 32 floats data + 16 pad = 48 (192B; row offset = 16 banks)
#define ROWF    48
#define TILE_F  (BM*ROWF)           // 6144 floats per tile
#define SMEM_GEMM (4*TILE_F*4)      // 98304 bytes (A0,A1,X0,X1)

typedef unsigned long long ull;

// 4x4 transpose permutation within each aligned 16-block of the K dim:
// logical i -> (i&3)*4 + (i>>2).  Makes {tg, tg+4, tg+8, tg+12} adjacent,
// so ONE LDS.128 feeds the fragments of TWO m16n8k8 steps.
__host__ __device__ __forceinline__ int perm16(int m) {
    return (m & ~15) | ((m & 3) << 2) | ((m >> 2) & 3);
}

// ---------------- device scratch ----------------
__device__ __align__(16) float g_W2[COUTC * MTOT];             // tf32 W [c][m_phys]
__device__ __align__(16) float g_XA[(size_t)QTOT * MTOT];      // tf32 folded input [q][m_phys]
__device__ __align__(16) float g_z [(size_t)NB * COUTC * QQ];  // pre-BN activations
__device__ float g_zb  [COUTC * VV];
__device__ float g_psum[COUTC * NPART];
__device__ float g_psq [COUTC * NPART];
__device__ float g_ss  [2 * COUTC];

// ---------------- helpers ----------------
__device__ __forceinline__ uint32_t smem_u32(const void* p) {
    uint32_t a;
    asm("{ .reg .u64 t; cvta.to.shared.u64 t, %1; cvt.u32.u64 %0, t; }" : "=r"(a) : "l"(p));
    return a;
}
__device__ __forceinline__ ull pack2(float lo, float hi) {
    ull r; asm("mov.b64 %0, {%1,%2};" : "=l"(r) : "f"(lo), "f"(hi)); return r;
}
__device__ __forceinline__ void unpack2(ull a, float &lo, float &hi) {
    asm("mov.b64 {%0,%1}, %2;" : "=f"(lo), "=f"(hi) : "l"(a));
}
__device__ __forceinline__ ull fma2(ull a, ull b, ull c) {
    ull d; asm("fma.rn.f32x2 %0, %1, %2, %3;" : "=l"(d) : "l"(a), "l"(b), "l"(c)); return d;
}
__device__ __forceinline__ float totf32(float f) {
    uint32_t u; asm("cvt.rna.tf32.f32 %0, %1;" : "=r"(u) : "f"(f));
    return __uint_as_float(u);
}

#define CP_ASYNC16(dst, src) \
    asm volatile("cp.async.cg.shared.global [%0], [%1], 16;" :: "r"(dst), "l"(src))
#define CP_COMMIT() asm volatile("cp.async.commit_group;" ::: "memory")
#define CP_WAIT1()  asm volatile("cp.async.wait_group 1;"  ::: "memory")

__device__ __forceinline__ void mma_tf32(float* c, uint32_t a0, uint32_t a1, uint32_t a2,
                                         uint32_t a3, uint32_t b0, uint32_t b1) {
    asm volatile(
        "mma.sync.aligned.m16n8k8.row.col.f32.tf32.tf32.f32 "
        "{%0,%1,%2,%3}, {%4,%5,%6,%7}, {%8,%9}, {%0,%1,%2,%3};"
        : "+f"(c[0]), "+f"(c[1]), "+f"(c[2]), "+f"(c[3])
        : "r"(a0), "r"(a1), "r"(a2), "r"(a3), "r"(b0), "r"(b1));
}

// ---------------- kernel: W re-layout (tf32 + k-perm16) ----------------
__global__ void k_w2(const float* __restrict__ W) {
    const int o = blockIdx.x;
    const int ci = threadIdx.x;
    const int c = o & 255, k = o >> 8;
    g_W2[c * MTOT + k * 256 + perm16(ci)] = totf32(W[o * 256 + ci]);
}

// ---------------- kernel: bias fold term ----------------
__global__ void k_zb(const float* __restrict__ A, const float* __restrict__ b) {
    const int w = blockIdx.x;
    const int c = threadIdx.x;
    float s = 0.f;
    for (int k = 0; k < KK; k++) {
        float sa = 0.f;
        for (int v = 0; v < VV; v++) sa += A[(k * VV + v) * VV + w];
        s += b[k * 256 + c] * sa;
    }
    g_zb[c * VV + w] = s;
}

// ---------------- kernel: fold adjacency into input (tf32 + k-perm16) ----------------
__global__ __launch_bounds__(128) void k_prep(const float* __restrict__ x,
                                              const float* __restrict__ A) {
    __shared__ ull As2[KK][VV][13];
    const int bx = blockIdx.x;
    const int n = bx >> 7;
    const int t = bx & (TT - 1);
    const int tid = threadIdx.x;
    const int pt = perm16(tid);          // tid<128: perm16(tid+128) = 128+pt

    for (int i = tid; i < KK * VV * 13; i += 128) {
        int k = i / (VV * 13);
        int r = i - k * (VV * 13);
        int v = r / 13, j = r - v * 13;
        float lo = A[(k * VV + v) * VV + 2 * j];
        float hi = (2 * j + 1 < VV) ? A[(k * VV + v) * VV + 2 * j + 1] : 0.f;
        As2[k][v][j] = pack2(lo, hi);
    }

    float xa[VV], xb[VV];
    {
        const float* pa = x + ((size_t)(n * CIN + tid) * TT + t) * VV;
        const float* pb = x + ((size_t)(n * CIN + tid + 128) * TT + t) * VV;
        #pragma unroll
        for (int v = 0; v < VV; v++) { xa[v] = pa[v]; xb[v] = pb[v]; }
    }
    __syncthreads();

    for (int k = 0; k < KK; k++) {
        ull za[13], zq[13];
        #pragma unroll
        for (int j = 0; j < 13; j++) { za[j] = 0ull; zq[j] = 0ull; }
        for (int v = 0; v < VV; v++) {
            const ull a2 = pack2(xa[v], xa[v]);
            const ull b2 = pack2(xb[v], xb[v]);
            #pragma unroll
            for (int j = 0; j < 13; j++) {
                const ull m = As2[k][v][j];
                za[j] = fma2(a2, m, za[j]);
                zq[j] = fma2(b2, m, zq[j]);
            }
        }
        const size_t rowbase = ((size_t)n * QQ + t * VV) * MTOT + k * 256;
        #pragma unroll
        for (int j = 0; j < 13; j++) {
            float lo, hi;
            unpack2(za[j], lo, hi);
            g_XA[rowbase + (size_t)(2 * j) * MTOT + pt] = totf32(lo);
            if (2 * j + 1 < VV) g_XA[rowbase + (size_t)(2 * j + 1) * MTOT + pt] = totf32(hi);
            unpack2(zq[j], lo, hi);
            g_XA[rowbase + (size_t)(2 * j) * MTOT + 128 + pt] = totf32(lo);
            if (2 * j + 1 < VV) g_XA[rowbase + (size_t)(2 * j + 1) * MTOT + 128 + pt] = totf32(hi);
        }
    }
}

// ---------------- kernel: warp-MMA tf32 GEMM + fused epilogue ----------------
__global__ __launch_bounds__(256, 2) void k_gemm() {
    extern __shared__ float sm[];
    float* Asm = sm;
    float* Xsm = sm + 2 * TILE_F;

    const int tid  = threadIdx.x;
    const int wid  = tid >> 5;
    const int lane = tid & 31;
    const int gid  = lane >> 2;
    const int tg   = lane & 3;
    const int wm   = wid >> 2;       // 0..1 -> 64 c-rows
    const int wn   = wid & 3;        // 0..3 -> 32 q-cols

    const int c0 = blockIdx.x * BM;
    const int q0 = blockIdx.y * BNQ;
    const int n    = q0 / QQ;
    const int qloc = q0 - n * QQ;

    const int lrow = tid >> 3;
    const int lc4  = tid & 7;
    const uint32_t sbase = smem_u32(sm);

    auto load_tiles = [&](int kc, int s) {
        const float* ga = g_W2 + (size_t)(c0 + lrow) * MTOT + kc * BK + lc4 * 4;
        const float* gx = g_XA + (size_t)(q0 + lrow) * MTOT + kc * BK + lc4 * 4;
        uint32_t da = sbase + (uint32_t)(s * TILE_F + lrow * ROWF + lc4 * 4) * 4;
        uint32_t dx = sbase + (uint32_t)((2 + s) * TILE_F + lrow * ROWF + lc4 * 4) * 4;
        #pragma unroll
        for (int u = 0; u < 4; u++) {
            CP_ASYNC16(da + u * 32 * ROWF * 4, ga + (size_t)u * 32 * MTOT);
            CP_ASYNC16(dx + u * 32 * ROWF * 4, gx + (size_t)u * 32 * MTOT);
        }
    };

    float acc[4][4][4];
    #pragma unroll
    for (int mf = 0; mf < 4; mf++)
        #pragma unroll
        for (int nf = 0; nf < 4; nf++)
            #pragma unroll
            for (int j = 0; j < 4; j++) acc[mf][nf][j] = 0.f;

    load_tiles(0, 0);
    CP_COMMIT();

    for (int kc = 0; kc < NKC; kc++) {
        const int s = kc & 1;
        if (kc + 1 < NKC) load_tiles(kc + 1, s ^ 1);
        CP_COMMIT();
        CP_WAIT1();
        __syncthreads();

        const float* AbRow = Asm + s * TILE_F + (wm * 64 + gid) * ROWF;
        const float* XbRow = Xsm + s * TILE_F + (wn * 32 + gid) * ROWF;
        #pragma unroll
        for (int k16 = 0; k16 < 2; k16++) {
            const int bo = k16 * 16 + tg * 4;
            // one LDS.128 per row feeds BOTH k8 steps of this k16 block
            float4 alo[4], ahi[4], bx[4];
            #pragma unroll
            for (int mf = 0; mf < 4; mf++) {
                alo[mf] = *(const float4*)(AbRow + mf * 16 * ROWF + bo);
                ahi[mf] = *(const float4*)(AbRow + mf * 16 * ROWF + 8 * ROWF + bo);
            }
            #pragma unroll
            for (int nf = 0; nf < 4; nf++)
                bx[nf] = *(const float4*)(XbRow + nf * 8 * ROWF + bo);
            // step a: logical k in [k16*16, k16*16+8)
            #pragma unroll
            for (int mf = 0; mf < 4; mf++)
                #pragma unroll
                for (int nf = 0; nf < 4; nf++)
                    mma_tf32(acc[mf][nf],
                             __float_as_uint(alo[mf].x), __float_as_uint(ahi[mf].x),
                             __float_as_uint(alo[mf].y), __float_as_uint(ahi[mf].y),
                             __float_as_uint(bx[nf].x),  __float_as_uint(bx[nf].y));
            // step b: logical k in [k16*16+8, k16*16+16)
            #pragma unroll
            for (int mf = 0; mf < 4; mf++)
                #pragma unroll
                for (int nf = 0; nf < 4; nf++)
                    mma_tf32(acc[mf][nf],
                             __float_as_uint(alo[mf].z), __float_as_uint(ahi[mf].z),
                             __float_as_uint(alo[mf].w), __float_as_uint(ahi[mf].w),
                             __float_as_uint(bx[nf].z),  __float_as_uint(bx[nf].w));
        }
        __syncthreads();
    }

    // ---- epilogue: +zb, z write, BN partials ----
    float s1[4][2], s2[4][2];
    #pragma unroll
    for (int mf = 0; mf < 4; mf++) { s1[mf][0] = s1[mf][1] = 0.f; s2[mf][0] = s2[mf][1] = 0.f; }

    #pragma unroll
    for (int mf = 0; mf < 4; mf++) {
        const int r0 = c0 + wm * 64 + mf * 16 + gid;
        #pragma unroll
        for (int nf = 0; nf < 4; nf++) {
            const int col = qloc + wn * 32 + nf * 8 + tg * 2;
            const int w0 = col % VV;
            const int w1 = (w0 + 1 == VV) ? 0 : w0 + 1;
            const float zb00 = g_zb[r0 * VV + w0],       zb01 = g_zb[r0 * VV + w1];
            const float zb10 = g_zb[(r0 + 8) * VV + w0], zb11 = g_zb[(r0 + 8) * VV + w1];
            float v00 = acc[mf][nf][0] + zb00;
            float v01 = acc[mf][nf][1] + zb01;
            float v10 = acc[mf][nf][2] + zb10;
            float v11 = acc[mf][nf][3] + zb11;
            s1[mf][0] += v00 + v01;  s2[mf][0] += v00 * v00 + v01 * v01;
            s1[mf][1] += v10 + v11;  s2[mf][1] += v10 * v10 + v11 * v11;
            float* zp0 = g_z + (size_t)(n * COUTC + r0) * QQ + col;
            float* zp1 = g_z + (size_t)(n * COUTC + r0 + 8) * QQ + col;
            *(float2*)zp0 = make_float2(v00, v01);
            *(float2*)zp1 = make_float2(v10, v11);
        }
    }
    #pragma unroll
    for (int mf = 0; mf < 4; mf++)
        #pragma unroll
        for (int h = 0; h < 2; h++) {
            s1[mf][h] += __shfl_xor_sync(0xffffffffu, s1[mf][h], 1);
            s1[mf][h] += __shfl_xor_sync(0xffffffffu, s1[mf][h], 2);
            s2[mf][h] += __shfl_xor_sync(0xffffffffu, s2[mf][h], 1);
            s2[mf][h] += __shfl_xor_sync(0xffffffffu, s2[mf][h], 2);
        }
    if (tg == 0) {
        const int slot = blockIdx.y * 4 + wn;
        #pragma unroll
        for (int mf = 0; mf < 4; mf++)
            #pragma unroll
            for (int h = 0; h < 2; h++) {
                const int r = c0 + wm * 64 + mf * 16 + gid + h * 8;
                g_psum[r * NPART + slot] = s1[mf][h];
                g_psq [r * NPART + slot] = s2[mf][h];
            }
    }
}

// ---------------- kernel: finalize BN stats ----------------
__global__ void k_stats(const float* __restrict__ gamma, const float* __restrict__ beta) {
    const int c = blockIdx.x;
    const int tid = threadIdx.x;
    float s1 = 0.f, s2 = 0.f;
    const float* ps = g_psum + c * NPART;
    const float* pq = g_psq  + c * NPART;
    for (int i = tid; i < NPART; i += 256) { s1 += ps[i]; s2 += pq[i]; }
    __shared__ float r1[256], r2[256];
    r1[tid] = s1; r2[tid] = s2;
    __syncthreads();
    for (int s = 128; s > 0; s >>= 1) {
        if (tid < s) { r1[tid] += r1[tid + s]; r2[tid] += r2[tid + s]; }
        __syncthreads();
    }
    if (tid == 0) {
        const float inv  = 1.0f / (float)CNT;
        const float mean = r1[0] * inv;
        const float var  = r2[0] * inv - mean * mean;
        const float sc   = gamma[c] * rsqrtf(var + BN_EPS);
        g_ss[c]         = sc;
        g_ss[COUTC + c] = beta[c] - mean * sc;
    }
}

// ---------------- kernel: normalize + ReLU ----------------
__global__ void k_norm(float* __restrict__ out) {
    const int i4 = blockIdx.x * blockDim.x + threadIdx.x;
    const int c = (i4 / 800) & (COUTC - 1);
    const float sc = g_ss[c];
    const float sh = g_ss[COUTC + c];
    const float4 z = ((const float4*)g_z)[i4];
    float4 o;
    o.x = fmaxf(0.f, fmaf(z.x, sc, sh));
    o.y = fmaxf(0.f, fmaf(z.y, sc, sh));
    o.z = fmaxf(0.f, fmaf(z.z, sc, sh));
    o.w = fmaxf(0.f, fmaf(z.w, sc, sh));
    ((float4*)out)[i4] = o;
}

// ---------------- launch ----------------
extern "C" void kernel_launch(void* const* d_in, const int* in_sizes, int n_in,
                              void* d_out, int out_size) {
    const float* x     = (const float*)d_in[0];
    const float* A     = (const float*)d_in[1];
    const float* W     = (const float*)d_in[2];
    const float* b     = (const float*)d_in[3];
    const float* gamma = (const float*)d_in[4];
    const float* beta  = (const float*)d_in[5];
    float* out = (float*)d_out;

    cudaFuncSetAttribute(k_gemm, cudaFuncAttributeMaxDynamicSharedMemorySize, SMEM_GEMM);

    k_w2  <<<MTOT, 256>>>(W);
    k_zb  <<<VV, 256>>>(A, b);
    k_prep<<<NB * TT, 128>>>(x, A);
    k_gemm<<<dim3(2, NQT2), 256, SMEM_GEMM>>>();
    k_stats<<<COUTC, 256>>>(gamma, beta);
    k_norm<<<(NB * COUTC * TT * VV / 4) / 256, 256>>>(out);
}

// round 9
// speedup vs baseline: 1.8196x; 1.0469x over previous
#include <cuda_runtime.h>
#include <cstdint>

// ---------------- problem constants ----------------
#define NB    32
#define CIN   256
#define COUTC 256
#define TT    128
#define VV    25
#define KK    3
#define QQ    (TT*VV)       // 3200 pixels per n
#define QTOT  (NB*QQ)       // 102400
#define MTOT  768           // reduction dim m = (k,ci)
#define BN_EPS 1e-5f
#define CNT   (NB*TT*VV)

// ---------------- GEMM tiling ----------------
#define BM    128
#define BNQ   128
#define BK    32
#define NKC   24            // 768/32
#define NQT2  800           // 102400/128
#define NPART 3200

// fragment-order tiles: A chunk 4096 floats (16KB), X chunk 4096 floats (16KB)
#define TILE_F  4096
#define SMEM_GEMM (4*TILE_F*4)      // 65536 bytes: A0,A1,X0,X1

typedef unsigned long long ull;

// ---------------- device scratch ----------------
// W2 fragment order: [R=c/16 (16)][K=m/8 (96)][quad=gid*4+tlo (32)][pos (4)]
//   pos = (c>>3 &1) + 2*(m>>2 &1);  gid=c&7, tlo=m&3
__device__ __align__(16) float g_W2[COUTC * MTOT];
// XA fragment order: [Nb=q/8 (12800)][k16=m/16 (48)][quad=gid*4+tlo (32)][pos (4)]
//   pos = (m>>3 &1)*2 + (m>>2 &1);  gid=q&7, tlo=m&3
__device__ __align__(16) float g_XA[(size_t)QTOT * MTOT];
__device__ __align__(16) float g_z [(size_t)NB * COUTC * QQ];
__device__ float g_zb  [COUTC * VV];
__device__ float g_psum[COUTC * NPART];
__device__ float g_psq [COUTC * NPART];
__device__ float g_ss  [2 * COUTC];

// ---------------- helpers ----------------
__device__ __forceinline__ uint32_t smem_u32(const void* p) {
    uint32_t a;
    asm("{ .reg .u64 t; cvta.to.shared.u64 t, %1; cvt.u32.u64 %0, t; }" : "=r"(a) : "l"(p));
    return a;
}
__device__ __forceinline__ ull pack2(float lo, float hi) {
    ull r; asm("mov.b64 %0, {%1,%2};" : "=l"(r) : "f"(lo), "f"(hi)); return r;
}
__device__ __forceinline__ void unpack2(ull a, float &lo, float &hi) {
    asm("mov.b64 {%0,%1}, %2;" : "=f"(lo), "=f"(hi) : "l"(a));
}
__device__ __forceinline__ ull fma2(ull a, ull b, ull c) {
    ull d; asm("fma.rn.f32x2 %0, %1, %2, %3;" : "=l"(d) : "l"(a), "l"(b), "l"(c)); return d;
}
__device__ __forceinline__ float totf32(float f) {
    uint32_t u; asm("cvt.rna.tf32.f32 %0, %1;" : "=r"(u) : "f"(f));
    return __uint_as_float(u);
}

#define CP_ASYNC16(dst, src) \
    asm volatile("cp.async.cg.shared.global [%0], [%1], 16;" :: "r"(dst), "l"(src))
#define CP_COMMIT() asm volatile("cp.async.commit_group;" ::: "memory")
#define CP_WAIT1()  asm volatile("cp.async.wait_group 1;"  ::: "memory")

__device__ __forceinline__ void mma_tf32(float* c, uint32_t a0, uint32_t a1, uint32_t a2,
                                         uint32_t a3, uint32_t b0, uint32_t b1) {
    asm volatile(
        "mma.sync.aligned.m16n8k8.row.col.f32.tf32.tf32.f32 "
        "{%0,%1,%2,%3}, {%4,%5,%6,%7}, {%8,%9}, {%0,%1,%2,%3};"
        : "+f"(c[0]), "+f"(c[1]), "+f"(c[2]), "+f"(c[3])
        : "r"(a0), "r"(a1), "r"(a2), "r"(a3), "r"(b0), "r"(b1));
}

// fragment-order index for W2: element (c, m)
__device__ __forceinline__ size_t w2f_idx(int c, int m) {
    return (((size_t)(c >> 4) * 96 + (m >> 3)) * 32 + (c & 7) * 4 + (m & 3)) * 4
           + ((c >> 3) & 1) + 2 * ((m >> 2) & 1);
}

// ---------------- kernel: W re-layout (tf32 + fragment order) ----------------
__global__ void k_w2(const float* __restrict__ W) {
    const int o = blockIdx.x;            // 0..767
    const int ci = threadIdx.x;
    const int c = o & 255, k = o >> 8;
    const int m = k * 256 + ci;
    g_W2[w2f_idx(c, m)] = totf32(W[o * 256 + ci]);
}

// ---------------- kernel: bias fold term ----------------
__global__ void k_zb(const float* __restrict__ A, const float* __restrict__ b) {
    const int w = blockIdx.x;
    const int c = threadIdx.x;
    float s = 0.f;
    for (int k = 0; k < KK; k++) {
        float sa = 0.f;
        for (int v = 0; v < VV; v++) sa += A[(k * VV + v) * VV + w];
        s += b[k * 256 + c] * sa;
    }
    g_zb[c * VV + w] = s;
}

// ---------------- kernel: fold adjacency into input (tf32 + fragment order) ----------------
__global__ __launch_bounds__(128) void k_prep(const float* __restrict__ x,
                                              const float* __restrict__ A) {
    __shared__ ull As2[KK][VV][13];
    const int bx = blockIdx.x;
    const int n = bx >> 7;
    const int t = bx & (TT - 1);
    const int tid = threadIdx.x;

    for (int i = tid; i < KK * VV * 13; i += 128) {
        int k = i / (VV * 13);
        int r = i - k * (VV * 13);
        int v = r / 13, j = r - v * 13;
        float lo = A[(k * VV + v) * VV + 2 * j];
        float hi = (2 * j + 1 < VV) ? A[(k * VV + v) * VV + 2 * j + 1] : 0.f;
        As2[k][v][j] = pack2(lo, hi);
    }

    float xa[VV], xb[VV];
    {
        const float* pa = x + ((size_t)(n * CIN + tid) * TT + t) * VV;
        const float* pb = x + ((size_t)(n * CIN + tid + 128) * TT + t) * VV;
        #pragma unroll
        for (int v = 0; v < VV; v++) { xa[v] = pa[v]; xb[v] = pb[v]; }
    }
    __syncthreads();

    const int qbase = n * QQ + t * VV;   // global pixel base for this (n,t)

    for (int k = 0; k < KK; k++) {
        ull za[13], zq[13];
        #pragma unroll
        for (int j = 0; j < 13; j++) { za[j] = 0ull; zq[j] = 0ull; }
        for (int v = 0; v < VV; v++) {
            const ull a2 = pack2(xa[v], xa[v]);
            const ull b2 = pack2(xb[v], xb[v]);
            #pragma unroll
            for (int j = 0; j < 13; j++) {
                const ull m = As2[k][v][j];
                za[j] = fma2(a2, m, za[j]);
                zq[j] = fma2(b2, m, zq[j]);
            }
        }
        // per-m constant part of fragment offset: m1 = k*256+tid, m2 = m1+128
        const int m1 = k * 256 + tid;
        const size_t koff1 = (size_t)(m1 >> 4) * 128 + (m1 & 3) * 4
                             + ((m1 >> 3) & 1) * 2 + ((m1 >> 2) & 1);
        const size_t koff2 = koff1 + 8 * 128;   // (m+128)>>4 = +8 k16 blocks
        float va[26], vb[26];
        #pragma unroll
        for (int j = 0; j < 13; j++) {
            unpack2(za[j], va[2 * j], va[2 * j + 1]);
            unpack2(zq[j], vb[2 * j], vb[2 * j + 1]);
        }
        #pragma unroll
        for (int w = 0; w < VV; w++) {
            const int qc = qbase + w;
            const size_t base = (size_t)(qc >> 3) * 6144 + (qc & 7) * 16;
            g_XA[base + koff1] = totf32(va[w]);
            g_XA[base + koff2] = totf32(vb[w]);
        }
    }
}

// ---------------- kernel: warp-MMA tf32 GEMM + fused epilogue ----------------
__global__ __launch_bounds__(256, 2) void k_gemm() {
    extern __shared__ float sm[];
    // linear fragment-order tiles: A s=0/1 at sm + s*TILE_F, X at sm + (2+s)*TILE_F

    const int tid  = threadIdx.x;
    const int wid  = tid >> 5;
    const int lane = tid & 31;
    const int gid  = lane >> 2;
    const int tg   = lane & 3;
    const int wm   = wid >> 2;       // 0..1 -> 64 c-rows
    const int wn   = wid & 3;        // 0..3 -> 32 q-cols

    const int c0 = blockIdx.x * BM;
    const int q0 = blockIdx.y * BNQ;
    const int n    = q0 / QQ;
    const int qloc = q0 - n * QQ;
    const int Rb0  = c0 >> 4;        // first 16-row block
    const int Nb0  = q0 >> 3;        // first 8-col block

    const uint32_t sbase = smem_u32(sm);

    auto load_tiles = [&](int kc, int s) {
        #pragma unroll
        for (int u = 0; u < 4; u++) {
            const int i16 = tid + u * 256;        // 0..1023
            const int f0  = i16 * 4;
            // A: [R(8)][Ksub(4)][quad(32)][pos(4)] -> 512 floats per R
            const int Ra   = f0 >> 9;
            const int rema = f0 & 511;
            const float* ga = g_W2 + ((size_t)(Rb0 + Ra) * 96 + kc * 4) * 128 + rema;
            CP_ASYNC16(sbase + (uint32_t)(s * TILE_F + f0) * 4, ga);
            // X: [Nb(16)][k16(2)][quad(32)][pos(4)] -> 256 floats per Nb
            const int Nbx  = f0 >> 8;
            const int remx = f0 & 255;
            const float* gx = g_XA + ((size_t)(Nb0 + Nbx) * 48 + kc * 2) * 128 + remx;
            CP_ASYNC16(sbase + (uint32_t)((2 + s) * TILE_F + f0) * 4, gx);
        }
    };

    float acc[4][4][4];
    #pragma unroll
    for (int mf = 0; mf < 4; mf++)
        #pragma unroll
        for (int nf = 0; nf < 4; nf++)
            #pragma unroll
            for (int j = 0; j < 4; j++) acc[mf][nf][j] = 0.f;

    load_tiles(0, 0);
    CP_COMMIT();

    for (int kc = 0; kc < NKC; kc++) {
        const int s = kc & 1;
        if (kc + 1 < NKC) load_tiles(kc + 1, s ^ 1);
        CP_COMMIT();
        CP_WAIT1();
        __syncthreads();

        const float* Ab = sm + s * TILE_F;
        const float* Xb = sm + (2 + s) * TILE_F;
        #pragma unroll
        for (int k16 = 0; k16 < 2; k16++) {
            // B quads: one LDS.128 per nf covers both k8 halves of this k16
            uint4 bq[4];
            #pragma unroll
            for (int nf = 0; nf < 4; nf++)
                bq[nf] = *(const uint4*)(Xb + (((wn * 4 + nf) * 2 + k16) * 32 + lane) * 4);
            #pragma unroll
            for (int half = 0; half < 2; half++) {
                const int k8 = k16 * 2 + half;
                uint4 aq[4];
                #pragma unroll
                for (int mf = 0; mf < 4; mf++)
                    aq[mf] = *(const uint4*)(Ab + (((wm * 4 + mf) * 4 + k8) * 32 + lane) * 4);
                if (half == 0) {
                    #pragma unroll
                    for (int mf = 0; mf < 4; mf++)
                        #pragma unroll
                        for (int nf = 0; nf < 4; nf++)
                            mma_tf32(acc[mf][nf], aq[mf].x, aq[mf].y, aq[mf].z, aq[mf].w,
                                     bq[nf].x, bq[nf].y);
                } else {
                    #pragma unroll
                    for (int mf = 0; mf < 4; mf++)
                        #pragma unroll
                        for (int nf = 0; nf < 4; nf++)
                            mma_tf32(acc[mf][nf], aq[mf].x, aq[mf].y, aq[mf].z, aq[mf].w,
                                     bq[nf].z, bq[nf].w);
                }
            }
        }
        __syncthreads();
    }

    // ---- epilogue: +zb, z write, BN partials ----
    float s1[4][2], s2[4][2];
    #pragma unroll
    for (int mf = 0; mf < 4; mf++) { s1[mf][0] = s1[mf][1] = 0.f; s2[mf][0] = s2[mf][1] = 0.f; }

    #pragma unroll
    for (int mf = 0; mf < 4; mf++) {
        const int r0 = c0 + wm * 64 + mf * 16 + gid;
        #pragma unroll
        for (int nf = 0; nf < 4; nf++) {
            const int col = qloc + wn * 32 + nf * 8 + tg * 2;
            const int w0 = col % VV;
            const int w1 = (w0 + 1 == VV) ? 0 : w0 + 1;
            const float zb00 = g_zb[r0 * VV + w0],       zb01 = g_zb[r0 * VV + w1];
            const float zb10 = g_zb[(r0 + 8) * VV + w0], zb11 = g_zb[(r0 + 8) * VV + w1];
            float v00 = acc[mf][nf][0] + zb00;
            float v01 = acc[mf][nf][1] + zb01;
            float v10 = acc[mf][nf][2] + zb10;
            float v11 = acc[mf][nf][3] + zb11;
            s1[mf][0] += v00 + v01;  s2[mf][0] += v00 * v00 + v01 * v01;
            s1[mf][1] += v10 + v11;  s2[mf][1] += v10 * v10 + v11 * v11;
            float* zp0 = g_z + (size_t)(n * COUTC + r0) * QQ + col;
            float* zp1 = g_z + (size_t)(n * COUTC + r0 + 8) * QQ + col;
            *(float2*)zp0 = make_float2(v00, v01);
            *(float2*)zp1 = make_float2(v10, v11);
        }
    }
    #pragma unroll
    for (int mf = 0; mf < 4; mf++)
        #pragma unroll
        for (int h = 0; h < 2; h++) {
            s1[mf][h] += __shfl_xor_sync(0xffffffffu, s1[mf][h], 1);
            s1[mf][h] += __shfl_xor_sync(0xffffffffu, s1[mf][h], 2);
            s2[mf][h] += __shfl_xor_sync(0xffffffffu, s2[mf][h], 1);
            s2[mf][h] += __shfl_xor_sync(0xffffffffu, s2[mf][h], 2);
        }
    if (tg == 0) {
        const int slot = blockIdx.y * 4 + wn;
        #pragma unroll
        for (int mf = 0; mf < 4; mf++)
            #pragma unroll
            for (int h = 0; h < 2; h++) {
                const int r = c0 + wm * 64 + mf * 16 + gid + h * 8;
                g_psum[r * NPART + slot] = s1[mf][h];
                g_psq [r * NPART + slot] = s2[mf][h];
            }
    }
}

// ---------------- kernel: finalize BN stats ----------------
__global__ void k_stats(const float* __restrict__ gamma, const float* __restrict__ beta) {
    const int c = blockIdx.x;
    const int tid = threadIdx.x;
    float s1 = 0.f, s2 = 0.f;
    const float* ps = g_psum + c * NPART;
    const float* pq = g_psq  + c * NPART;
    for (int i = tid; i < NPART; i += 256) { s1 += ps[i]; s2 += pq[i]; }
    __shared__ float r1[256], r2[256];
    r1[tid] = s1; r2[tid] = s2;
    __syncthreads();
    for (int s = 128; s > 0; s >>= 1) {
        if (tid < s) { r1[tid] += r1[tid + s]; r2[tid] += r2[tid + s]; }
        __syncthreads();
    }
    if (tid == 0) {
        const float inv  = 1.0f / (float)CNT;
        const float mean = r1[0] * inv;
        const float var  = r2[0] * inv - mean * mean;
        const float sc   = gamma[c] * rsqrtf(var + BN_EPS);
        g_ss[c]         = sc;
        g_ss[COUTC + c] = beta[c] - mean * sc;
    }
}

// ---------------- kernel: normalize + ReLU ----------------
__global__ void k_norm(float* __restrict__ out) {
    const int i4 = blockIdx.x * blockDim.x + threadIdx.x;
    const int c = (i4 / 800) & (COUTC - 1);
    const float sc = g_ss[c];
    const float sh = g_ss[COUTC + c];
    const float4 z = ((const float4*)g_z)[i4];
    float4 o;
    o.x = fmaxf(0.f, fmaf(z.x, sc, sh));
    o.y = fmaxf(0.f, fmaf(z.y, sc, sh));
    o.z = fmaxf(0.f, fmaf(z.z, sc, sh));
    o.w = fmaxf(0.f, fmaf(z.w, sc, sh));
    ((float4*)out)[i4] = o;
}

// ---------------- launch ----------------
extern "C" void kernel_launch(void* const* d_in, const int* in_sizes, int n_in,
                              void* d_out, int out_size) {
    const float* x     = (const float*)d_in[0];
    const float* A     = (const float*)d_in[1];
    const float* W     = (const float*)d_in[2];
    const float* b     = (const float*)d_in[3];
    const float* gamma = (const float*)d_in[4];
    const float* beta  = (const float*)d_in[5];
    float* out = (float*)d_out;

    cudaFuncSetAttribute(k_gemm, cudaFuncAttributeMaxDynamicSharedMemorySize, SMEM_GEMM);

    k_w2  <<<MTOT, 256>>>(W);
    k_zb  <<<VV, 256>>>(A, b);
    k_prep<<<NB * TT, 128>>>(x, A);
    k_gemm<<<dim3(2, NQT2), 256, SMEM_GEMM>>>();
    k_stats<<<COUTC, 256>>>(gamma, beta);
    k_norm<<<(NB * COUTC * TT * VV / 4) / 256, 256>>>(out);
}